// round 15
// baseline (speedup 1.0000x reference)
#include <cuda_runtime.h>
#include <cuda_bf16.h>
#include <cstddef>
#include <cstdint>

// Problem constants: N=50000, DEG=32, E=N*32, F=64, K=3, DIM=2, L=3
#define MAXN 50000
#define MAXE (MAXN * 32)
#define FDIM 64
#define KF   192        // K * F
#define TILE 64

// smem: gs[64][192] only (staging lives inside the rows being gathered)
#define GS_FLOATS (TILE * KF)
#define SMEM_BYTES  (GS_FLOATS * 4 + 1024)   // 50176 B -> 4 CTAs/SM (200KB)

__device__ float h_bufA[(size_t)MAXN * FDIM];
__device__ float h_bufB[(size_t)MAXN * FDIM];
// WP[layer][pp][t] float4 = {Wk[2pp][2t], Wk[2pp+1][2t], Wk[2pp][2t+1], Wk[2pp+1][2t+1]}
__device__ float WP_buf[3 * 96 * 32 * 4];
// wpack[layer][e] = {w0, w1, w2, bitcast(src)}
__device__ float4 wpack_buf[(size_t)3 * MAXE];

// Packed fp32x2 FMA (sm_103a FFMA2 — only reachable via PTX)
#define FMA_F32X2(d, a, b, c) \
    asm("fma.rn.f32x2 %0, %1, %2, %3;" : "=l"(d) : "l"(a), "l"(b), "l"(c))
#define PACK_DUP(d, x) \
    asm("mov.b64 %0, {%1, %1};" : "=l"(d) : "f"(x))
#define UNPACK2(lo, hi, v) \
    asm("mov.b64 {%0, %1}, %2;" : "=f"(lo), "=f"(hi) : "l"(v))

typedef unsigned long long ull;

// ---------------------------------------------------------------------------
// Prep 1: per-edge Gaussian weights for every layer.
// ---------------------------------------------------------------------------
__global__ void prep_w(const float* __restrict__ pseudo,
                       const int*   __restrict__ colind,
                       const float* __restrict__ projW,
                       const float* __restrict__ projb,
                       const float* __restrict__ mu,
                       const float* __restrict__ isg,
                       int nE, int nL)
{
    const int idx = blockIdx.x * 256 + threadIdx.x;
    if (idx >= nE * nL) return;
    const int i = idx / nE;
    const int e = idx - i * nE;

    const float W00 = __ldg(&projW[i*4+0]), W01 = __ldg(&projW[i*4+1]);
    const float W10 = __ldg(&projW[i*4+2]), W11 = __ldg(&projW[i*4+3]);
    const float b0 = __ldg(&projb[i*2+0]), b1 = __ldg(&projb[i*2+1]);

    const float2 ps = __ldg(&((const float2*)pseudo)[e]);
    const float u0 = tanhf(fmaf(ps.y, W10, fmaf(ps.x, W00, b0)));
    const float u1 = tanhf(fmaf(ps.y, W11, fmaf(ps.x, W01, b1)));

    float4 v;
    {
        float q0 = __ldg(&isg[i*6+0]), q1 = __ldg(&isg[i*6+1]);
        float d0 = u0 - __ldg(&mu[i*6+0]), d1 = u1 - __ldg(&mu[i*6+1]);
        v.x = __expf(-0.5f * (d0*d0*q0*q0 + d1*d1*q1*q1));
        q0 = __ldg(&isg[i*6+2]); q1 = __ldg(&isg[i*6+3]);
        d0 = u0 - __ldg(&mu[i*6+2]); d1 = u1 - __ldg(&mu[i*6+3]);
        v.y = __expf(-0.5f * (d0*d0*q0*q0 + d1*d1*q1*q1));
        q0 = __ldg(&isg[i*6+4]); q1 = __ldg(&isg[i*6+5]);
        d0 = u0 - __ldg(&mu[i*6+4]); d1 = u1 - __ldg(&mu[i*6+5]);
        v.z = __expf(-0.5f * (d0*d0*q0*q0 + d1*d1*q1*q1));
    }
    v.w = __int_as_float(__ldg(&colind[e]));
    wpack_buf[(size_t)i * nE + e] = v;
}

// ---------------------------------------------------------------------------
// Prep 2: rearrange fcW into WP layout (K-pair-packed, warp-coalesced).
// ---------------------------------------------------------------------------
__global__ void prep_kernel(const float* __restrict__ fcW, int nL)
{
    const int idx = blockIdx.x * 256 + threadIdx.x;
    const int total = nL * 96 * 32;
    if (idx >= total) return;
    const int i  = idx / (96 * 32);
    const int rem = idx - i * 96 * 32;
    const int pp = rem >> 5, t = rem & 31;
    const float* W = fcW + i * 64 * 192;
    const int p0 = 2 * pp, p1 = 2 * pp + 1;
    const int k0 = p0 >> 6, j0 = p0 & 63;
    const int k1 = p1 >> 6, j1 = p1 & 63;
    float4 v;
    v.x = W[j0 * 192 + k0 * 64 + 2 * t];
    v.y = W[j1 * 192 + k1 * 64 + 2 * t];
    v.z = W[j0 * 192 + k0 * 64 + 2 * t + 1];
    v.w = W[j1 * 192 + k1 * 64 + 2 * t + 1];
    ((float4*)WP_buf)[idx] = v;
}

// ---------------------------------------------------------------------------
// Fused layer kernel (4 CTAs/SM = 32 warps).
//   Phase A: stage all 8 nodes' wpack up front (inline with degree check),
//            then 4 half-warp pair-gathers back-to-back.
//   Phase B: block GEMM: g LDS.128 broadcast + W coalesced LDG (L1).
// ---------------------------------------------------------------------------
__global__ __launch_bounds__(256, 4)
void fused_layer(const float* __restrict__ h,
                 const int*   __restrict__ rowptr,
                 const float4* __restrict__ wpack,   // [E] this layer
                 const float* __restrict__ WP,       // [96][32] float4
                 float* __restrict__ out, int n)
{
    extern __shared__ float smem[];
    float* gs = smem;                               // [64][192]

    const int tid = threadIdx.x;
    const int wid = tid >> 5;
    const int lid = tid & 31;

    const ulonglong2* __restrict__ wpv = (const ulonglong2*)WP;

    // phase-A lane mapping
    const int half = lid >> 4;        // 0 = node A, 1 = node B
    const int fl   = lid & 15;        // feature group 4fl..4fl+3

    // phase-B mapping
    const int tx = tid & 31;          // cols 2tx, 2tx+1
    const int ty = tid >> 5;          // rows 8ty..+7

    const int rbase = wid << 3;

    const int ntiles = (n + TILE - 1) / TILE;
    for (int tile = blockIdx.x; tile < ntiles; tile += gridDim.x) {
        const int r0 = tile * TILE;
        const int rows = min(TILE, n - r0);
        __syncthreads();   // prev phase-B readers done

        // ---------------- Phase A ---------------------------------------
        {
            // stage all 8 nodes' wpack rows inline with the degree check
            bool fast = (r0 + rbase + 8 <= n);
            if (fast) {
                #pragma unroll
                for (int s = 0; s < 8; s++) {
                    const int nd = r0 + rbase + s;
                    const int a = __ldg(&rowptr[nd]);
                    const int b = __ldg(&rowptr[nd + 1]);
                    if (b - a == 32)
                        ((float4*)(gs + (rbase + s) * KF))[lid] =
                            __ldg(&wpack[a + lid]);
                    else
                        fast = false;
                }
            }

            if (fast) {
                __syncwarp();
                #pragma unroll
                for (int jp = 0; jp < 4; jp++) {
                    const int rA = rbase + (jp << 1);
                    const float4* stg = (const float4*)(gs + (rA + half) * KF);
                    const float* hb = h + 4 * fl;
                    ull a0l = 0ULL, a0h = 0ULL, a1l = 0ULL, a1h = 0ULL,
                        a2l = 0ULL, a2h = 0ULL;

                    #pragma unroll 8
                    for (int t = 0; t < 32; t++) {
                        const float4 wt = stg[t];
                        const int src = __float_as_int(wt.w);
                        const ulonglong2 hv =
                            *(const ulonglong2*)(hb + (size_t)src * FDIM);
                        ull w0d, w1d, w2d;
                        PACK_DUP(w0d, wt.x); PACK_DUP(w1d, wt.y); PACK_DUP(w2d, wt.z);
                        FMA_F32X2(a0l, hv.x, w0d, a0l);
                        FMA_F32X2(a0h, hv.y, w0d, a0h);
                        FMA_F32X2(a1l, hv.x, w1d, a1l);
                        FMA_F32X2(a1h, hv.y, w1d, a1h);
                        FMA_F32X2(a2l, hv.x, w2d, a2l);
                        FMA_F32X2(a2h, hv.y, w2d, a2h);
                    }
                    __syncwarp();   // all lanes done reading rows rA, rA+1

                    float* grow = gs + (rA + half) * KF + 4 * fl;
                    ulonglong2 v;
                    v.x = a0l; v.y = a0h; *(ulonglong2*)(grow      ) = v;
                    v.x = a1l; v.y = a1h; *(ulonglong2*)(grow +  64) = v;
                    v.x = a2l; v.y = a2h; *(ulonglong2*)(grow + 128) = v;
                }
            } else {
                // general fallback: per node, float2 lanes, restage in own row
                for (int s = 0; s < 8; s++) {
                    const int node = r0 + rbase + s;
                    if (node >= n) break;
                    float4* stage = (float4*)(gs + (rbase + s) * KF);
                    const int e0 = __ldg(&rowptr[node]);
                    const int e1 = __ldg(&rowptr[node + 1]);
                    ull A0 = 0ULL, A1 = 0ULL, A2 = 0ULL;
                    for (int base = e0; base < e1; base += 32) {
                        const int cnt = min(32, e1 - base);
                        if (lid < cnt)
                            stage[lid] = __ldg(&wpack[base + lid]);
                        __syncwarp();
                        for (int t = 0; t < cnt; t++) {
                            const float4 wt = stage[t];
                            const int src = __float_as_int(wt.w);
                            const ull hv = *(const ull*)(h + (size_t)src * FDIM + 2 * lid);
                            ull w0d, w1d, w2d;
                            PACK_DUP(w0d, wt.x); PACK_DUP(w1d, wt.y); PACK_DUP(w2d, wt.z);
                            FMA_F32X2(A0, hv, w0d, A0);
                            FMA_F32X2(A1, hv, w1d, A1);
                            FMA_F32X2(A2, hv, w2d, A2);
                        }
                        __syncwarp();
                    }
                    *(ull*)(gs + (rbase + s) * KF + 2 * lid      ) = A0;
                    *(ull*)(gs + (rbase + s) * KF + 2 * lid +  64) = A1;
                    *(ull*)(gs + (rbase + s) * KF + 2 * lid + 128) = A2;
                    __syncwarp();
                }
            }
        }
        __syncthreads();

        // ---------------- Phase B: GEMM ----------------------------------
        {
            const ull* gp = (const ull*)(gs + (ty << 3) * KF);

            ull acc[8][2];
            #pragma unroll
            for (int i = 0; i < 8; i++) { acc[i][0] = 0ULL; acc[i][1] = 0ULL; }

            #pragma unroll 2
            for (int pp2 = 0; pp2 < 48; pp2++) {
                const ulonglong2 wA = __ldg(&wpv[(2 * pp2    ) * 32 + tx]);
                const ulonglong2 wB = __ldg(&wpv[(2 * pp2 + 1) * 32 + tx]);
                #pragma unroll
                for (int i = 0; i < 8; i++) {
                    const ulonglong2 gv = *(const ulonglong2*)(gp + i * 96 + 2 * pp2);
                    FMA_F32X2(acc[i][0], gv.x, wA.x, acc[i][0]);
                    FMA_F32X2(acc[i][1], gv.x, wA.y, acc[i][1]);
                    FMA_F32X2(acc[i][0], gv.y, wB.x, acc[i][0]);
                    FMA_F32X2(acc[i][1], gv.y, wB.y, acc[i][1]);
                }
            }

            #pragma unroll
            for (int i = 0; i < 8; i++) {
                const int r = (ty << 3) + i;
                if (r < rows) {
                    float e0, o0, e1, o1;
                    UNPACK2(e0, o0, acc[i][0]);
                    UNPACK2(e1, o1, acc[i][1]);
                    *(float2*)&out[(size_t)(r0 + r) * FDIM + 2 * tx] =
                        make_float2(e0 + o0, e1 + o1);
                }
            }
        }
    }
}

// ---------------------------------------------------------------------------
extern "C" void kernel_launch(void* const* d_in, const int* in_sizes, int n_in,
                              void* d_out, int out_size)
{
    const float* feat   = (const float*)d_in[0];
    const float* pseudo = (const float*)d_in[1];
    const int*   rowptr = (const int*)  d_in[2];
    const int*   colind = (const int*)  d_in[3];
    const float* projW  = (const float*)d_in[4];
    const float* projb  = (const float*)d_in[5];
    const float* fcW    = (const float*)d_in[6];
    const float* mu     = (const float*)d_in[7];
    const float* isg    = (const float*)d_in[8];

    const int n  = in_sizes[0] / FDIM;
    const int nE = in_sizes[3];
    const int nL = in_sizes[6] / (FDIM * KF);

    void *hap, *hbp, *wpp, *wkp;
    cudaGetSymbolAddress(&hap, h_bufA);
    cudaGetSymbolAddress(&hbp, h_bufB);
    cudaGetSymbolAddress(&wpp, WP_buf);
    cudaGetSymbolAddress(&wkp, wpack_buf);
    float* hbufs[2] = { (float*)hap, (float*)hbp };
    const float* WP = (const float*)wpp;
    const float4* wpack = (const float4*)wkp;

    cudaFuncSetAttribute(fused_layer, cudaFuncAttributeMaxDynamicSharedMemorySize, SMEM_BYTES);

    prep_kernel<<<(nL * 96 * 32 + 255) / 256, 256>>>(fcW, nL);
    prep_w<<<((size_t)nE * nL + 255) / 256, 256>>>(pseudo, colind, projW, projb,
                                                   mu, isg, nE, nL);

    const int ntiles = (n + TILE - 1) / TILE;
    const int maxg = 4 * 148;
    const int grid = ntiles < maxg ? ntiles : maxg;

    const float* hin = feat;
    for (int i = 0; i < nL; i++) {
        float* hout = (i == nL - 1) ? (float*)d_out : hbufs[i & 1];
        fused_layer<<<grid, 256, SMEM_BYTES>>>(hin, rowptr,
                                               wpack + (size_t)i * nE,
                                               WP + (size_t)i * 96 * 32 * 4,
                                               hout, n);
        hin = hout;
    }
}

// round 17
// speedup vs baseline: 1.1667x; 1.1667x over previous
#include <cuda_runtime.h>
#include <cuda_bf16.h>
#include <cstddef>
#include <cstdint>

// Problem constants: N=50000, DEG=32, E=N*32, F=64, K=3, DIM=2, L=3
#define MAXN 50000
#define MAXE (MAXN * 32)
#define FDIM 64
#define KF   192        // K * F
#define TILE 64

// smem: gs[64][192] only (per-warp slabs; staging lives inside the rows)
#define GS_FLOATS (TILE * KF)
#define SMEM_BYTES  (GS_FLOATS * 4 + 1024)   // 50176 B -> 3 CTAs/SM

__device__ float h_bufA[(size_t)MAXN * FDIM];
__device__ float h_bufB[(size_t)MAXN * FDIM];
// WP[layer][pp][t] float4 = {Wk[2pp][2t], Wk[2pp+1][2t], Wk[2pp][2t+1], Wk[2pp+1][2t+1]}
__device__ float WP_buf[3 * 96 * 32 * 4];
// wpack[layer][e] = {w0, w1, w2, bitcast(src)}
__device__ float4 wpack_buf[(size_t)3 * MAXE];

// Packed fp32x2 FMA (sm_103a FFMA2 — only reachable via PTX)
#define FMA_F32X2(d, a, b, c) \
    asm("fma.rn.f32x2 %0, %1, %2, %3;" : "=l"(d) : "l"(a), "l"(b), "l"(c))
#define PACK_DUP(d, x) \
    asm("mov.b64 %0, {%1, %1};" : "=l"(d) : "f"(x))
#define UNPACK2(lo, hi, v) \
    asm("mov.b64 {%0, %1}, %2;" : "=f"(lo), "=f"(hi) : "l"(v))

typedef unsigned long long ull;

// ---------------------------------------------------------------------------
// Prep 1: per-edge Gaussian weights, ALL layers in one pass over the edges.
// ---------------------------------------------------------------------------
__global__ void prep_w(const float* __restrict__ pseudo,
                       const int*   __restrict__ colind,
                       const float* __restrict__ projW,
                       const float* __restrict__ projb,
                       const float* __restrict__ mu,
                       const float* __restrict__ isg,
                       int nE, int nL)
{
    const int e = blockIdx.x * 256 + threadIdx.x;
    if (e >= nE) return;
    const float2 ps = __ldg(&((const float2*)pseudo)[e]);
    const float srcf = __int_as_float(__ldg(&colind[e]));

    for (int i = 0; i < nL; i++) {
        const float W00 = __ldg(&projW[i*4+0]), W01 = __ldg(&projW[i*4+1]);
        const float W10 = __ldg(&projW[i*4+2]), W11 = __ldg(&projW[i*4+3]);
        const float b0 = __ldg(&projb[i*2+0]), b1 = __ldg(&projb[i*2+1]);
        const float u0 = tanhf(fmaf(ps.y, W10, fmaf(ps.x, W00, b0)));
        const float u1 = tanhf(fmaf(ps.y, W11, fmaf(ps.x, W01, b1)));

        float4 v;
        float q0 = __ldg(&isg[i*6+0]), q1 = __ldg(&isg[i*6+1]);
        float d0 = u0 - __ldg(&mu[i*6+0]), d1 = u1 - __ldg(&mu[i*6+1]);
        v.x = __expf(-0.5f * (d0*d0*q0*q0 + d1*d1*q1*q1));
        q0 = __ldg(&isg[i*6+2]); q1 = __ldg(&isg[i*6+3]);
        d0 = u0 - __ldg(&mu[i*6+2]); d1 = u1 - __ldg(&mu[i*6+3]);
        v.y = __expf(-0.5f * (d0*d0*q0*q0 + d1*d1*q1*q1));
        q0 = __ldg(&isg[i*6+4]); q1 = __ldg(&isg[i*6+5]);
        d0 = u0 - __ldg(&mu[i*6+4]); d1 = u1 - __ldg(&mu[i*6+5]);
        v.z = __expf(-0.5f * (d0*d0*q0*q0 + d1*d1*q1*q1));
        v.w = srcf;
        wpack_buf[(size_t)i * nE + e] = v;
    }
}

// ---------------------------------------------------------------------------
// Prep 2: rearrange fcW into WP layout (K-pair-packed, warp-coalesced).
// ---------------------------------------------------------------------------
__global__ void prep_kernel(const float* __restrict__ fcW, int nL)
{
    const int idx = blockIdx.x * 256 + threadIdx.x;
    const int total = nL * 96 * 32;
    if (idx >= total) return;
    const int i  = idx / (96 * 32);
    const int rem = idx - i * 96 * 32;
    const int pp = rem >> 5, t = rem & 31;
    const float* W = fcW + i * 64 * 192;
    const int p0 = 2 * pp, p1 = 2 * pp + 1;
    const int k0 = p0 >> 6, j0 = p0 & 63;
    const int k1 = p1 >> 6, j1 = p1 & 63;
    float4 v;
    v.x = W[j0 * 192 + k0 * 64 + 2 * t];
    v.y = W[j1 * 192 + k1 * 64 + 2 * t];
    v.z = W[j0 * 192 + k0 * 64 + 2 * t + 1];
    v.w = W[j1 * 192 + k1 * 64 + 2 * t + 1];
    ((float4*)WP_buf)[idx] = v;
}

// ---------------------------------------------------------------------------
// Fused layer kernel — WARP-PRIVATE tiles, no block barriers.
// Each warp: stage 8 nodes' wpack -> 4 half-warp pair-gathers -> GEMM its
// own 8 rows -> store. Warps free-run; gather (L2) and GEMM (FFMA2) phases
// from different warps overlap continuously on the SM.
// ---------------------------------------------------------------------------
__global__ __launch_bounds__(256, 3)
void fused_layer(const float* __restrict__ h,
                 const int*   __restrict__ rowptr,
                 const float4* __restrict__ wpack,   // [E] this layer
                 const float* __restrict__ WP,       // [96][32] float4
                 float* __restrict__ out, int n)
{
    extern __shared__ float smem[];
    float* gs = smem;                               // [64][192], warp slab = 8 rows

    const int tid = threadIdx.x;
    const int wid = tid >> 5;
    const int lid = tid & 31;

    const ulonglong2* __restrict__ wpv = (const ulonglong2*)WP;

    // phase-A lane mapping
    const int half = lid >> 4;        // 0 = node A, 1 = node B
    const int fl   = lid & 15;        // feature group 4fl..4fl+3

    const int rbase = wid << 3;
    float* slab = gs + rbase * KF;    // this warp's 8 rows

    const int ntiles = (n + TILE - 1) / TILE;
    for (int tile = blockIdx.x; tile < ntiles; tile += gridDim.x) {
        const int r0 = tile * TILE;

        // ---------------- Phase A (warp-private) -------------------------
        bool fast = (r0 + rbase + 8 <= n);
        int e0s[8];
        if (fast) {
            #pragma unroll
            for (int s = 0; s < 8; s++) {
                const int nd = r0 + rbase + s;
                const int a = __ldg(&rowptr[nd]);
                const int b = __ldg(&rowptr[nd + 1]);
                e0s[s] = a;
                fast = fast && (b - a == 32);
            }
        }

        if (fast) {
            // stage all 8 nodes' wpack into their own slab rows (512B each)
            #pragma unroll
            for (int s = 0; s < 8; s++)
                ((float4*)(slab + s * KF))[lid] = __ldg(&wpack[e0s[s] + lid]);
            __syncwarp();

            #pragma unroll
            for (int jp = 0; jp < 4; jp++) {
                const int rA = jp << 1;
                const float4* stg = (const float4*)(slab + (rA + half) * KF);
                const float* hb = h + 4 * fl;
                ull a0l = 0ULL, a0h = 0ULL, a1l = 0ULL, a1h = 0ULL,
                    a2l = 0ULL, a2h = 0ULL;

                #pragma unroll 8
                for (int t = 0; t < 32; t++) {
                    const float4 wt = stg[t];
                    const int src = __float_as_int(wt.w);
                    const ulonglong2 hv =
                        *(const ulonglong2*)(hb + (size_t)src * FDIM);
                    ull w0d, w1d, w2d;
                    PACK_DUP(w0d, wt.x); PACK_DUP(w1d, wt.y); PACK_DUP(w2d, wt.z);
                    FMA_F32X2(a0l, hv.x, w0d, a0l);
                    FMA_F32X2(a0h, hv.y, w0d, a0h);
                    FMA_F32X2(a1l, hv.x, w1d, a1l);
                    FMA_F32X2(a1h, hv.y, w1d, a1h);
                    FMA_F32X2(a2l, hv.x, w2d, a2l);
                    FMA_F32X2(a2h, hv.y, w2d, a2h);
                }
                __syncwarp();   // all lanes done reading slab rows rA, rA+1

                float* grow = slab + (rA + half) * KF + 4 * fl;
                ulonglong2 v;
                v.x = a0l; v.y = a0h; *(ulonglong2*)(grow      ) = v;
                v.x = a1l; v.y = a1h; *(ulonglong2*)(grow +  64) = v;
                v.x = a2l; v.y = a2h; *(ulonglong2*)(grow + 128) = v;
            }
            __syncwarp();
        } else {
            // general fallback: per node, 2 features/lane, stage in own row
            for (int s = 0; s < 8; s++) {
                const int node = r0 + rbase + s;
                if (node >= n) break;
                float4* stage = (float4*)(slab + s * KF);
                const int e0 = __ldg(&rowptr[node]);
                const int e1 = __ldg(&rowptr[node + 1]);
                ull A0 = 0ULL, A1 = 0ULL, A2 = 0ULL;
                for (int base = e0; base < e1; base += 32) {
                    const int cnt = min(32, e1 - base);
                    if (lid < cnt)
                        stage[lid] = __ldg(&wpack[base + lid]);
                    __syncwarp();
                    for (int t = 0; t < cnt; t++) {
                        const float4 wt = stage[t];
                        const int src = __float_as_int(wt.w);
                        const ull hv = *(const ull*)(h + (size_t)src * FDIM + 2 * lid);
                        ull w0d, w1d, w2d;
                        PACK_DUP(w0d, wt.x); PACK_DUP(w1d, wt.y); PACK_DUP(w2d, wt.z);
                        FMA_F32X2(A0, hv, w0d, A0);
                        FMA_F32X2(A1, hv, w1d, A1);
                        FMA_F32X2(A2, hv, w2d, A2);
                    }
                    __syncwarp();
                }
                *(ull*)(slab + s * KF + 2 * lid      ) = A0;
                *(ull*)(slab + s * KF + 2 * lid +  64) = A1;
                *(ull*)(slab + s * KF + 2 * lid + 128) = A2;
                __syncwarp();
            }
        }

        // ---------------- Phase B: GEMM of this warp's 8 rows -------------
        {
            const ull* gp = (const ull*)slab;

            ull acc[8][2];
            #pragma unroll
            for (int i = 0; i < 8; i++) { acc[i][0] = 0ULL; acc[i][1] = 0ULL; }

            #pragma unroll 2
            for (int pp2 = 0; pp2 < 48; pp2++) {
                const ulonglong2 wA = __ldg(&wpv[(2 * pp2    ) * 32 + lid]);
                const ulonglong2 wB = __ldg(&wpv[(2 * pp2 + 1) * 32 + lid]);
                #pragma unroll
                for (int i = 0; i < 8; i++) {
                    const ulonglong2 gv = *(const ulonglong2*)(gp + i * 96 + 2 * pp2);
                    FMA_F32X2(acc[i][0], gv.x, wA.x, acc[i][0]);
                    FMA_F32X2(acc[i][1], gv.x, wA.y, acc[i][1]);
                    FMA_F32X2(acc[i][0], gv.y, wB.x, acc[i][0]);
                    FMA_F32X2(acc[i][1], gv.y, wB.y, acc[i][1]);
                }
            }

            #pragma unroll
            for (int i = 0; i < 8; i++) {
                const int r = r0 + rbase + i;
                if (r < n) {
                    float e0, o0, e1, o1;
                    UNPACK2(e0, o0, acc[i][0]);
                    UNPACK2(e1, o1, acc[i][1]);
                    *(float2*)&out[(size_t)r * FDIM + 2 * lid] =
                        make_float2(e0 + o0, e1 + o1);
                }
            }
        }
        __syncwarp();   // slab reusable next iteration (warp-local)
    }
}

// ---------------------------------------------------------------------------
extern "C" void kernel_launch(void* const* d_in, const int* in_sizes, int n_in,
                              void* d_out, int out_size)
{
    const float* feat   = (const float*)d_in[0];
    const float* pseudo = (const float*)d_in[1];
    const int*   rowptr = (const int*)  d_in[2];
    const int*   colind = (const int*)  d_in[3];
    const float* projW  = (const float*)d_in[4];
    const float* projb  = (const float*)d_in[5];
    const float* fcW    = (const float*)d_in[6];
    const float* mu     = (const float*)d_in[7];
    const float* isg    = (const float*)d_in[8];

    const int n  = in_sizes[0] / FDIM;
    const int nE = in_sizes[3];
    const int nL = in_sizes[6] / (FDIM * KF);

    void *hap, *hbp, *wpp, *wkp;
    cudaGetSymbolAddress(&hap, h_bufA);
    cudaGetSymbolAddress(&hbp, h_bufB);
    cudaGetSymbolAddress(&wpp, WP_buf);
    cudaGetSymbolAddress(&wkp, wpack_buf);
    float* hbufs[2] = { (float*)hap, (float*)hbp };
    const float* WP = (const float*)wpp;
    const float4* wpack = (const float4*)wkp;

    cudaFuncSetAttribute(fused_layer, cudaFuncAttributeMaxDynamicSharedMemorySize, SMEM_BYTES);

    prep_kernel<<<(nL * 96 * 32 + 255) / 256, 256>>>(fcW, nL);
    prep_w<<<(nE + 255) / 256, 256>>>(pseudo, colind, projW, projb, mu, isg, nE, nL);

    const int ntiles = (n + TILE - 1) / TILE;
    const int maxg = 3 * 148;
    const int grid = ntiles < maxg ? ntiles : maxg;

    const float* hin = feat;
    for (int i = 0; i < nL; i++) {
        float* hout = (i == nL - 1) ? (float*)d_out : hbufs[i & 1];
        fused_layer<<<grid, 256, SMEM_BYTES>>>(hin, rowptr,
                                               wpack + (size_t)i * nE,
                                               WP + (size_t)i * 96 * 32 * 4,
                                               hout, n);
        hin = hout;
    }
}